// round 2
// baseline (speedup 1.0000x reference)
#include <cuda_runtime.h>
#include <math.h>

#define B_   2
#define S_   2048
#define HID  2048
#define NH   16
#define NKV  8
#define HD   128
#define MTOK (B_ * S_)          // 4096
#define SCALING 0.08838834764831845f

// ---------------- scratch (device globals; no runtime alloc allowed) ----------------
__device__ float g_qraw[MTOK * NH * HD];     // 4096 x 2048
__device__ float g_kraw[MTOK * NKV * HD];    // 4096 x 1024
__device__ float g_vraw[MTOK * NKV * HD];
__device__ float g_q[MTOK * NH * HD];        // [b][h][s][d]
__device__ float g_k[MTOK * NKV * HD];       // [b][kv][s][d]
__device__ float g_v[MTOK * NKV * HD];
__device__ float g_ao[MTOK * NH * HD];       // [b][s][h*d]
__device__ float g_delta[S_];
__device__ float g_post[S_];
__device__ float g_gamma[S_];
__device__ float g_eta[S_];

// ---------------- prep: prior -> p, gamma, eta, delta, post ----------------
__global__ __launch_bounds__(256) void prep_kernel(const float* __restrict__ prior) {
    __shared__ float red[8];
    int t = threadIdx.x;
    float s = 0.f;
    for (int i = t; i < S_; i += 256) s += prior[i];
    for (int o = 16; o; o >>= 1) s += __shfl_down_sync(0xffffffffu, s, o);
    if ((t & 31) == 0) red[t >> 5] = s;
    __syncthreads();
    float tot = 0.f;
    #pragma unroll
    for (int i = 0; i < 8; i++) tot += red[i];
    float inv = 1.f / tot;
    for (int i = t; i < S_; i += 256) {
        float p = prior[i] * inv;
        float c = p * (float)S_ - 1.f;
        float g = 1.f + 0.5f * c;
        g_gamma[i] = fminf(fmaxf(g, 0.8f), 1.25f);
        g_eta[i]   = fminf(fmaxf(g, 0.9f), 1.1f);
        g_delta[i] = fminf(fmaxf(logf(p + 1e-8f), -2.f), 2.f);   // BETA_BIAS=1, cap=2
        g_post[i]  = 0.5f * logf(p * (float)S_);                  // BETA_POST=0.5, log space
    }
}

// ---------------- SGEMM: C[M,N] = A[M,K] * B[K,N], all row-major ----------------
// 128x128 block, BK=8, 256 threads, 8x8 per thread.
__global__ __launch_bounds__(256) void sgemm_kernel(const float* __restrict__ A,
                                                    const float* __restrict__ Bw,
                                                    float* __restrict__ C, int N, int K) {
    __shared__ float As[8][128];
    __shared__ float Bs[8][128];
    int tid  = threadIdx.x;
    int row0 = blockIdx.y << 7;
    int col0 = blockIdx.x << 7;
    int ty = tid >> 4, tx = tid & 15;
    int arow = tid >> 1,        acol = (tid & 1) << 2;
    int brow = tid >> 5,        bcol = (tid & 31) << 2;
    const float* Ap = A  + (size_t)(row0 + arow) * K + acol;
    const float* Bp = Bw + (size_t)brow * N + col0 + bcol;

    float acc[8][8];
    #pragma unroll
    for (int i = 0; i < 8; i++)
        #pragma unroll
        for (int j = 0; j < 8; j++) acc[i][j] = 0.f;

    for (int k0 = 0; k0 < K; k0 += 8) {
        float4 av = *(const float4*)(Ap + k0);
        float4 bv = *(const float4*)(Bp + (size_t)k0 * N);
        As[acol + 0][arow] = av.x;
        As[acol + 1][arow] = av.y;
        As[acol + 2][arow] = av.z;
        As[acol + 3][arow] = av.w;
        *(float4*)&Bs[brow][bcol] = bv;
        __syncthreads();
        #pragma unroll
        for (int kk = 0; kk < 8; kk++) {
            float4 a0 = *(const float4*)&As[kk][ty << 3];
            float4 a1 = *(const float4*)&As[kk][(ty << 3) + 4];
            float4 b0 = *(const float4*)&Bs[kk][tx << 3];
            float4 b1 = *(const float4*)&Bs[kk][(tx << 3) + 4];
            float ra[8] = {a0.x, a0.y, a0.z, a0.w, a1.x, a1.y, a1.z, a1.w};
            float rb[8] = {b0.x, b0.y, b0.z, b0.w, b1.x, b1.y, b1.z, b1.w};
            #pragma unroll
            for (int i = 0; i < 8; i++)
                #pragma unroll
                for (int j = 0; j < 8; j++) acc[i][j] += ra[i] * rb[j];
        }
        __syncthreads();
    }
    #pragma unroll
    for (int i = 0; i < 8; i++) {
        float* Cp = C + (size_t)(row0 + (ty << 3) + i) * N + col0 + (tx << 3);
        #pragma unroll
        for (int j = 0; j < 8; j++) Cp[j] = acc[i][j];
    }
}

// ---------------- RMSnorm + RoPE + gamma/eta scale + transpose ----------------
// grid (MTOK, NH + 2*NKV), block 128. z<16: Q head, z<24: K head, else V head.
__global__ __launch_bounds__(128) void transform_kernel(const float* __restrict__ cosb,
                                                        const float* __restrict__ sinb,
                                                        const float* __restrict__ qw,
                                                        const float* __restrict__ kw) {
    int m = blockIdx.x;                 // token
    int z = blockIdx.y;
    int d = threadIdx.x;                // 0..127
    int b = m >> 11, s = m & 2047;

    __shared__ float sh[HD];
    __shared__ float red[4];

    if (z >= NH + NKV) {                // V: just eta scale + transpose
        int h = z - NH - NKV;
        float x = g_vraw[(size_t)m * (NKV * HD) + h * HD + d];
        g_v[((size_t)(b * NKV + h) * S_ + s) * HD + d] = x * g_eta[s];
        return;
    }

    int mode_q = (z < NH);
    int h = mode_q ? z : (z - NH);
    const float* src = mode_q ? (g_qraw + (size_t)m * (NH * HD) + h * HD)
                              : (g_kraw + (size_t)m * (NKV * HD) + h * HD);
    float x = src[d];
    sh[d] = x;
    float v2 = x * x;
    for (int o = 16; o; o >>= 1) v2 += __shfl_down_sync(0xffffffffu, v2, o);
    if ((d & 31) == 0) red[d >> 5] = v2;
    __syncthreads();
    float sum = red[0] + red[1] + red[2] + red[3];
    float rsq = rsqrtf(sum * (1.f / 128.f) + 1e-6f);
    const float* wn = mode_q ? qw : kw;
    float val = x * rsq * wn[d];
    float pv  = sh[d ^ 64] * rsq * wn[d ^ 64];
    float rot = (d < 64) ? -pv : pv;
    size_t ci = (size_t)m * HD + d;
    float o = val * cosb[ci] + rot * sinb[ci];
    if (mode_q)
        g_q[((size_t)(b * NH + h) * S_ + s) * HD + d] = o;
    else
        g_k[((size_t)(b * NKV + h) * S_ + s) * HD + d] = o * g_gamma[s];
}

// ---------------- causal flash attention, fp32, BQ=BK=64 ----------------
// grid (S/64, B*NH), 256 threads. Bias folded: bk[k] = m1[h]*delta[k] + m2[h]*post[k].
// smem (floats): Qt [128][68] (transposed), KVu union (Kt [128][68] / Vs [64][132]),
//                Ps [64][68], bk [64]  -> 21824 floats = 87296 B dynamic.
__global__ __launch_bounds__(256) void attn_kernel(const float* __restrict__ m1,
                                                   const float* __restrict__ m2) {
    extern __shared__ float sm[];
    float* Qt = sm;               // 8704 floats
    float* Kt = sm + 8704;        // 8704 (union with V tile)
    float* Ps = sm + 17408;       // 4352
    float* bk = sm + 21760;       // 64

    int bh = blockIdx.y;
    int b = bh >> 4, h = bh & 15, hk = h >> 1;
    int q0 = blockIdx.x << 6;
    int tid = threadIdx.x;
    int ty = tid >> 4, tx = tid & 15;

    const float4* Qg = (const float4*)(g_q + ((size_t)(b * NH + h) * S_ + q0) * HD);
    const float*  Kg = g_k + (size_t)(b * NKV + hk) * S_ * HD;
    const float*  Vg = g_v + (size_t)(b * NKV + hk) * S_ * HD;
    float m1h = m1[h], m2h = m2[h];

    // load Q tile transposed: Qt[d][r]
    for (int it = tid; it < 2048; it += 256) {
        int r = it >> 5, d4 = it & 31;
        float4 vq = Qg[r * 32 + d4];
        int base = (d4 * 4) * 68 + r;
        Qt[base]       = vq.x;
        Qt[base + 68]  = vq.y;
        Qt[base + 136] = vq.z;
        Qt[base + 204] = vq.w;
    }

    float mrow[4], lrow[4], O[4][8];
    #pragma unroll
    for (int i = 0; i < 4; i++) {
        mrow[i] = -3e38f; lrow[i] = 0.f;
        #pragma unroll
        for (int j = 0; j < 8; j++) O[i][j] = 0.f;
    }

    int nkt = (q0 >> 6) + 1;   // causal: only tiles with k0 <= q0
    for (int kt = 0; kt < nkt; kt++) {
        int k0 = kt << 6;
        __syncthreads();   // previous iteration's PV reads done
        const float4* Kg4 = (const float4*)(Kg + (size_t)k0 * HD);
        for (int it = tid; it < 2048; it += 256) {
            int r = it >> 5, d4 = it & 31;
            float4 vk = Kg4[r * 32 + d4];
            int base = (d4 * 4) * 68 + r;
            Kt[base]       = vk.x;
            Kt[base + 68]  = vk.y;
            Kt[base + 136] = vk.z;
            Kt[base + 204] = vk.w;
        }
        if (tid < 64) bk[tid] = m1h * g_delta[k0 + tid] + m2h * g_post[k0 + tid];
        __syncthreads();

        // S tile: rows ty*4.., cols tx*4..
        float S[4][4];
        #pragma unroll
        for (int i = 0; i < 4; i++)
            #pragma unroll
            for (int j = 0; j < 4; j++) S[i][j] = 0.f;
        #pragma unroll 4
        for (int d = 0; d < 128; d++) {
            float4 qa = *(const float4*)&Qt[d * 68 + (ty << 2)];
            float4 kb = *(const float4*)&Kt[d * 68 + (tx << 2)];
            float qr[4] = {qa.x, qa.y, qa.z, qa.w};
            float kr[4] = {kb.x, kb.y, kb.z, kb.w};
            #pragma unroll
            for (int i = 0; i < 4; i++)
                #pragma unroll
                for (int j = 0; j < 4; j++) S[i][j] += qr[i] * kr[j];
        }

        // scale + bias + causal mask, online softmax update
        float mnew[4];
        #pragma unroll
        for (int i = 0; i < 4; i++) {
            int qg = q0 + (ty << 2) + i;
            mnew[i] = mrow[i];
            #pragma unroll
            for (int j = 0; j < 4; j++) {
                int kg = k0 + (tx << 2) + j;
                float vv = S[i][j] * SCALING + bk[(tx << 2) + j];
                vv = (kg <= qg) ? vv : -3e38f;
                S[i][j] = vv;
                mnew[i] = fmaxf(mnew[i], vv);
            }
        }
        #pragma unroll
        for (int i = 0; i < 4; i++)
            for (int o = 8; o; o >>= 1)
                mnew[i] = fmaxf(mnew[i], __shfl_xor_sync(0xffffffffu, mnew[i], o));
        #pragma unroll
        for (int i = 0; i < 4; i++) {
            float pr = 0.f;
            #pragma unroll
            for (int j = 0; j < 4; j++) {
                float p = __expf(S[i][j] - mnew[i]);
                Ps[((ty << 2) + i) * 68 + (tx << 2) + j] = p;
                pr += p;
            }
            for (int o = 8; o; o >>= 1) pr += __shfl_xor_sync(0xffffffffu, pr, o);
            float sc = __expf(mrow[i] - mnew[i]);
            lrow[i] = lrow[i] * sc + pr;
            mrow[i] = mnew[i];
            #pragma unroll
            for (int j = 0; j < 8; j++) O[i][j] *= sc;
        }
        __syncthreads();   // Ps written, Kt reads done

        // load V tile into union buffer (row-major, stride 132 floats = 33 float4)
        const float4* Vg4 = (const float4*)(Vg + (size_t)k0 * HD);
        float4* Vs4 = (float4*)Kt;
        for (int it = tid; it < 2048; it += 256) {
            int r = it >> 5, d4 = it & 31;
            Vs4[r * 33 + d4] = Vg4[r * 32 + d4];
        }
        __syncthreads();

        // O += Ps @ V : rows ty*4.., d cols tx*8..
        #pragma unroll 4
        for (int kk = 0; kk < 64; kk++) {
            float4 v0 = Vs4[kk * 33 + (tx << 1)];
            float4 v1 = Vs4[kk * 33 + (tx << 1) + 1];
            #pragma unroll
            for (int i = 0; i < 4; i++) {
                float p = Ps[((ty << 2) + i) * 68 + kk];
                O[i][0] += p * v0.x; O[i][1] += p * v0.y;
                O[i][2] += p * v0.z; O[i][3] += p * v0.w;
                O[i][4] += p * v1.x; O[i][5] += p * v1.y;
                O[i][6] += p * v1.z; O[i][7] += p * v1.w;
            }
        }
    }

    #pragma unroll
    for (int i = 0; i < 4; i++) {
        int qg = q0 + (ty << 2) + i;
        float inv = 1.f / lrow[i];
        float* op = g_ao + (size_t)(b * S_ + qg) * (NH * HD) + h * HD + (tx << 3);
        #pragma unroll
        for (int j = 0; j < 8; j++) op[j] = O[i][j] * inv;
    }
}

// ---------------- launch ----------------
extern "C" void kernel_launch(void* const* d_in, const int* in_sizes, int n_in,
                              void* d_out, int out_size) {
    const float* hidden = (const float*)d_in[0];
    const float* cosb   = (const float*)d_in[1];
    const float* sinb   = (const float*)d_in[2];
    // d_in[3] = attention_mask (pure causal; implemented directly)
    const float* prior  = (const float*)d_in[4];
    const float* m1     = (const float*)d_in[5];
    const float* m2     = (const float*)d_in[6];
    const float* Wq     = (const float*)d_in[7];
    const float* Wk     = (const float*)d_in[8];
    const float* Wv     = (const float*)d_in[9];
    const float* Wo     = (const float*)d_in[10];
    const float* qw     = (const float*)d_in[11];
    const float* kw     = (const float*)d_in[12];
    float* out = (float*)d_out;

    float *qraw, *kraw, *vraw, *ao;
    cudaGetSymbolAddress((void**)&qraw, g_qraw);
    cudaGetSymbolAddress((void**)&kraw, g_kraw);
    cudaGetSymbolAddress((void**)&vraw, g_vraw);
    cudaGetSymbolAddress((void**)&ao,   g_ao);

    const int ATTN_SMEM = 21824 * 4;   // 87296 B
    cudaFuncSetAttribute(attn_kernel, cudaFuncAttributeMaxDynamicSharedMemorySize, ATTN_SMEM);

    prep_kernel<<<1, 256>>>(prior);

    sgemm_kernel<<<dim3(16, 32), 256>>>(hidden, Wq, qraw, 2048, 2048);
    sgemm_kernel<<<dim3(8, 32),  256>>>(hidden, Wk, kraw, 1024, 2048);
    sgemm_kernel<<<dim3(8, 32),  256>>>(hidden, Wv, vraw, 1024, 2048);

    transform_kernel<<<dim3(MTOK, NH + 2 * NKV), 128>>>(cosb, sinb, qw, kw);

    attn_kernel<<<dim3(S_ / 64, B_ * NH), 256, ATTN_SMEM>>>(m1, m2);

    sgemm_kernel<<<dim3(16, 32), 256>>>(ao, Wo, out, 2048, 2048);
}

// round 7
// speedup vs baseline: 1.6377x; 1.6377x over previous
#include <cuda_runtime.h>
#include <cuda_bf16.h>
#include <math.h>
#include <stdint.h>

#define B_   2
#define S_   2048
#define HID  2048
#define NH   16
#define NKV  8
#define HD   128
#define MTOK (B_ * S_)          // 4096
#define SCALING 0.08838834764831845f

// ---------------- scratch (device globals; no runtime alloc allowed) ----------------
__device__ float g_qraw[MTOK * NH * HD];
__device__ float g_kraw[MTOK * NKV * HD];
__device__ float g_vraw[MTOK * NKV * HD];
__device__ float g_q[MTOK * NH * HD];
__device__ float g_k[MTOK * NKV * HD];
__device__ float g_v[MTOK * NKV * HD];
__device__ float g_ao[MTOK * NH * HD];
__device__ float g_delta[S_];
__device__ float g_post[S_];
__device__ float g_gamma[S_];
__device__ float g_eta[S_];

// split-bf16 operands
__device__ __nv_bfloat16 g_ahi[MTOK * HID];
__device__ __nv_bfloat16 g_alo[MTOK * HID];
__device__ __nv_bfloat16 g_aoh[MTOK * HID];
__device__ __nv_bfloat16 g_aol[MTOK * HID];
__device__ __nv_bfloat16 g_wqt_h[HID * HID];
__device__ __nv_bfloat16 g_wqt_l[HID * HID];
__device__ __nv_bfloat16 g_wkt_h[NKV * HD * HID];
__device__ __nv_bfloat16 g_wkt_l[NKV * HD * HID];
__device__ __nv_bfloat16 g_wvt_h[NKV * HD * HID];
__device__ __nv_bfloat16 g_wvt_l[NKV * HD * HID];
__device__ __nv_bfloat16 g_wot_h[HID * HID];
__device__ __nv_bfloat16 g_wot_l[HID * HID];

__device__ __forceinline__ uint32_t smem_u32(const void* p) {
    uint32_t a;
    asm("{ .reg .u64 t; cvta.to.shared.u64 t, %1; cvt.u32.u64 %0, t; }" : "=r"(a) : "l"(p));
    return a;
}

// ---------------- prep: prior -> gamma/eta/delta/post ----------------
__global__ __launch_bounds__(256) void prep_kernel(const float* __restrict__ prior) {
    __shared__ float red[8];
    int t = threadIdx.x;
    float s = 0.f;
    for (int i = t; i < S_; i += 256) s += prior[i];
    for (int o = 16; o; o >>= 1) s += __shfl_down_sync(0xffffffffu, s, o);
    if ((t & 31) == 0) red[t >> 5] = s;
    __syncthreads();
    float tot = 0.f;
    #pragma unroll
    for (int i = 0; i < 8; i++) tot += red[i];
    float inv = 1.f / tot;
    for (int i = t; i < S_; i += 256) {
        float p = prior[i] * inv;
        float c = p * (float)S_ - 1.f;
        float g = 1.f + 0.5f * c;
        g_gamma[i] = fminf(fmaxf(g, 0.8f), 1.25f);
        g_eta[i]   = fminf(fmaxf(g, 0.9f), 1.1f);
        g_delta[i] = fminf(fmaxf(logf(p + 1e-8f), -2.f), 2.f);
        g_post[i]  = 0.5f * logf(p * (float)S_);
    }
}

// ---------------- elementwise fp32 -> (hi, lo) bf16 split ----------------
__global__ __launch_bounds__(256) void split_kernel(const float* __restrict__ x,
                                                    __nv_bfloat16* __restrict__ hi,
                                                    __nv_bfloat16* __restrict__ lo) {
    int i = (blockIdx.x * 256 + threadIdx.x) * 4;
    float4 v = *(const float4*)(x + i);
    float a0 = v.x, a1 = v.y, a2 = v.z, a3 = v.w;
    __nv_bfloat16 h0 = __float2bfloat16(a0), h1 = __float2bfloat16(a1);
    __nv_bfloat16 h2 = __float2bfloat16(a2), h3 = __float2bfloat16(a3);
    __nv_bfloat16 l0 = __float2bfloat16(a0 - __bfloat162float(h0));
    __nv_bfloat16 l1 = __float2bfloat16(a1 - __bfloat162float(h1));
    __nv_bfloat16 l2 = __float2bfloat16(a2 - __bfloat162float(h2));
    __nv_bfloat16 l3 = __float2bfloat16(a3 - __bfloat162float(h3));
    *(__nv_bfloat162*)(hi + i)     = __nv_bfloat162(h0, h1);
    *(__nv_bfloat162*)(hi + i + 2) = __nv_bfloat162(h2, h3);
    *(__nv_bfloat162*)(lo + i)     = __nv_bfloat162(l0, l1);
    *(__nv_bfloat162*)(lo + i + 2) = __nv_bfloat162(l2, l3);
}

// ---------------- transpose + split: W[K,N] f32 -> T[N,K] bf16 hi/lo ----------------
__global__ __launch_bounds__(256) void tsplit_kernel(const float* __restrict__ W,
                                                     __nv_bfloat16* __restrict__ Th,
                                                     __nv_bfloat16* __restrict__ Tl,
                                                     int K, int N) {
    __shared__ float ts[32][33];
    int tx = threadIdx.x & 31, ty = threadIdx.x >> 5;   // ty 0..7
    int k0 = blockIdx.y << 5, n0 = blockIdx.x << 5;
    #pragma unroll
    for (int i = 0; i < 4; i++)
        ts[ty + 8 * i][tx] = W[(size_t)(k0 + ty + 8 * i) * N + n0 + tx];
    __syncthreads();
    #pragma unroll
    for (int i = 0; i < 4; i++) {
        int nl = ty + 8 * i;
        float x = ts[tx][nl];
        __nv_bfloat16 h = __float2bfloat16(x);
        __nv_bfloat16 l = __float2bfloat16(x - __bfloat162float(h));
        size_t o = (size_t)(n0 + nl) * K + k0 + tx;
        Th[o] = h;
        Tl[o] = l;
    }
}

// ---------------- bf16 split GEMM via mma.sync (sm_100 baseline path) ----------------
// C[M,N] = A[M,K] * Bt[N,K]^T using 3-term split: AhBh + AhBl + AlBh.
// CTA 128x128, 256 threads (8 warps in 2x4), warp tile 64x32, BK=32.
// smem per stage: 4 tiles x 128 rows x 40 bf16 (80B padded rows) = 40960 B; x2 = 81920 B.
#define GPAD 40
#define GEMM_SMEM 81920
__global__ __launch_bounds__(256) void gemm_mma_kernel(
    const __nv_bfloat16* __restrict__ Ah, const __nv_bfloat16* __restrict__ Al,
    const __nv_bfloat16* __restrict__ Bh, const __nv_bfloat16* __restrict__ Bl,
    float* __restrict__ C, int N, int K)
{
    extern __shared__ char gsm[];
    uint32_t sb = smem_u32(gsm);
    int tid = threadIdx.x, w = tid >> 5, lane = tid & 31;
    int wm = (w >> 2) * 64, wn = (w & 3) * 32;
    int row0 = blockIdx.y << 7, col0 = blockIdx.x << 7;

    const __nv_bfloat16* gp[4] = {Ah, Al, Bh, Bl};

    // stage tile byte offsets: Ah 0, Al 10240, Bh 20480, Bl 30720; stage stride 40960
    auto stage_load = [&](int kc, int s) {
        uint32_t base = sb + (uint32_t)s * 40960u;
        #pragma unroll
        for (int i = 0; i < 8; i++) {
            int it = i * 256 + tid;           // 0..2047
            int t  = it >> 9;                 // tile 0..3
            int r  = (it >> 2) & 127;         // row
            int j  = it & 3;                  // 16B chunk (8 bf16)
            const __nv_bfloat16* g = gp[t] + (size_t)((t < 2 ? row0 : col0) + r) * K + kc + j * 8;
            uint32_t dst = base + (uint32_t)t * 10240u + (uint32_t)r * 80u + (uint32_t)j * 16u;
            asm volatile("cp.async.cg.shared.global [%0], [%1], 16;" :: "r"(dst), "l"(g));
        }
        asm volatile("cp.async.commit_group;");
    };

    float acc[4][4][4];
    #pragma unroll
    for (int a = 0; a < 4; a++)
        #pragma unroll
        for (int b = 0; b < 4; b++)
            #pragma unroll
            for (int c = 0; c < 4; c++) acc[a][b][c] = 0.f;

    stage_load(0, 0);

    for (int kc = 0; kc < K; kc += 32) {
        int s = (kc >> 5) & 1;
        if (kc + 32 < K) {
            stage_load(kc + 32, s ^ 1);
            asm volatile("cp.async.wait_group 1;");
        } else {
            asm volatile("cp.async.wait_group 0;");
        }
        __syncthreads();

        uint32_t base = sb + (uint32_t)s * 40960u;
        uint32_t ahB = base, alB = base + 10240u, bhB = base + 20480u, blB = base + 30720u;

        #pragma unroll
        for (int ks = 0; ks < 32; ks += 16) {
            // fragment smem addresses
            uint32_t aoff = (uint32_t)((lane & 15)) * 80u + (uint32_t)(ks + ((lane >> 4) << 3)) * 2u;
            uint32_t boff = (uint32_t)((lane & 7)) * 80u + (uint32_t)(ks + ((lane >> 3) & 1) * 8) * 2u;

            uint32_t ah[4][4], al[4][4], bh[4][2], bl[4][2];
            #pragma unroll
            for (int mt = 0; mt < 4; mt++) {
                uint32_t ra = (uint32_t)(wm + mt * 16) * 80u + aoff;
                asm volatile("ldmatrix.sync.aligned.m8n8.x4.shared.b16 {%0,%1,%2,%3}, [%4];"
                             : "=r"(ah[mt][0]), "=r"(ah[mt][1]), "=r"(ah[mt][2]), "=r"(ah[mt][3])
                             : "r"(ahB + ra));
                asm volatile("ldmatrix.sync.aligned.m8n8.x4.shared.b16 {%0,%1,%2,%3}, [%4];"
                             : "=r"(al[mt][0]), "=r"(al[mt][1]), "=r"(al[mt][2]), "=r"(al[mt][3])
                             : "r"(alB + ra));
            }
            #pragma unroll
            for (int nt = 0; nt < 4; nt++) {
                uint32_t rb = (uint32_t)(wn + nt * 8) * 80u + boff;
                asm volatile("ldmatrix.sync.aligned.m8n8.x2.shared.b16 {%0,%1}, [%2];"
                             : "=r"(bh[nt][0]), "=r"(bh[nt][1]) : "r"(bhB + rb));
                asm volatile("ldmatrix.sync.aligned.m8n8.x2.shared.b16 {%0,%1}, [%2];"
                             : "=r"(bl[nt][0]), "=r"(bl[nt][1]) : "r"(blB + rb));
            }
            #pragma unroll
            for (int mt = 0; mt < 4; mt++) {
                #pragma unroll
                for (int nt = 0; nt < 4; nt++) {
                    float* d = acc[mt][nt];
                    asm volatile("mma.sync.aligned.m16n8k16.row.col.f32.bf16.bf16.f32 "
                                 "{%0,%1,%2,%3}, {%4,%5,%6,%7}, {%8,%9}, {%0,%1,%2,%3};"
                                 : "+f"(d[0]), "+f"(d[1]), "+f"(d[2]), "+f"(d[3])
                                 : "r"(ah[mt][0]), "r"(ah[mt][1]), "r"(ah[mt][2]), "r"(ah[mt][3]),
                                   "r"(bh[nt][0]), "r"(bh[nt][1]));
                    asm volatile("mma.sync.aligned.m16n8k16.row.col.f32.bf16.bf16.f32 "
                                 "{%0,%1,%2,%3}, {%4,%5,%6,%7}, {%8,%9}, {%0,%1,%2,%3};"
                                 : "+f"(d[0]), "+f"(d[1]), "+f"(d[2]), "+f"(d[3])
                                 : "r"(ah[mt][0]), "r"(ah[mt][1]), "r"(ah[mt][2]), "r"(ah[mt][3]),
                                   "r"(bl[nt][0]), "r"(bl[nt][1]));
                    asm volatile("mma.sync.aligned.m16n8k16.row.col.f32.bf16.bf16.f32 "
                                 "{%0,%1,%2,%3}, {%4,%5,%6,%7}, {%8,%9}, {%0,%1,%2,%3};"
                                 : "+f"(d[0]), "+f"(d[1]), "+f"(d[2]), "+f"(d[3])
                                 : "r"(al[mt][0]), "r"(al[mt][1]), "r"(al[mt][2]), "r"(al[mt][3]),
                                   "r"(bh[nt][0]), "r"(bh[nt][1]));
                }
            }
        }
        __syncthreads();
    }

    // epilogue: c0,c1 -> (r = lane>>2, c = (lane&3)*2), c2,c3 -> r+8
    int er = lane >> 2, ec = (lane & 3) << 1;
    #pragma unroll
    for (int mt = 0; mt < 4; mt++) {
        #pragma unroll
        for (int nt = 0; nt < 4; nt++) {
            float* Cp = C + (size_t)(row0 + wm + mt * 16 + er) * N + col0 + wn + nt * 8 + ec;
            *(float2*)Cp           = make_float2(acc[mt][nt][0], acc[mt][nt][1]);
            *(float2*)(Cp + 8 * N) = make_float2(acc[mt][nt][2], acc[mt][nt][3]);
        }
    }
}

// ---------------- RMSnorm + RoPE + gamma/eta scale + transpose ----------------
__global__ __launch_bounds__(128) void transform_kernel(const float* __restrict__ cosb,
                                                        const float* __restrict__ sinb,
                                                        const float* __restrict__ qw,
                                                        const float* __restrict__ kw) {
    int m = blockIdx.x;
    int z = blockIdx.y;
    int d = threadIdx.x;
    int b = m >> 11, s = m & 2047;

    __shared__ float sh[HD];
    __shared__ float red[4];

    if (z >= NH + NKV) {
        int h = z - NH - NKV;
        float x = g_vraw[(size_t)m * (NKV * HD) + h * HD + d];
        g_v[((size_t)(b * NKV + h) * S_ + s) * HD + d] = x * g_eta[s];
        return;
    }
    int mode_q = (z < NH);
    int h = mode_q ? z : (z - NH);
    const float* src = mode_q ? (g_qraw + (size_t)m * (NH * HD) + h * HD)
                              : (g_kraw + (size_t)m * (NKV * HD) + h * HD);
    float x = src[d];
    sh[d] = x;
    float v2 = x * x;
    for (int o = 16; o; o >>= 1) v2 += __shfl_down_sync(0xffffffffu, v2, o);
    if ((d & 31) == 0) red[d >> 5] = v2;
    __syncthreads();
    float sum = red[0] + red[1] + red[2] + red[3];
    float rsq = rsqrtf(sum * (1.f / 128.f) + 1e-6f);
    const float* wn = mode_q ? qw : kw;
    float val = x * rsq * wn[d];
    float pv  = sh[d ^ 64] * rsq * wn[d ^ 64];
    float rot = (d < 64) ? -pv : pv;
    size_t ci = (size_t)m * HD + d;
    float o = val * cosb[ci] + rot * sinb[ci];
    if (mode_q)
        g_q[((size_t)(b * NH + h) * S_ + s) * HD + d] = o;
    else
        g_k[((size_t)(b * NKV + h) * S_ + s) * HD + d] = o * g_gamma[s];
}

// ---------------- causal flash attention, fp32, BQ=BK=64 ----------------
__global__ __launch_bounds__(256) void attn_kernel(const float* __restrict__ m1,
                                                   const float* __restrict__ m2) {
    extern __shared__ float sm[];
    float* Qt = sm;               // 8704 floats
    float* Kt = sm + 8704;        // 8704 (union with V tile)
    float* Ps = sm + 17408;       // 4352
    float* bk = sm + 21760;       // 64

    int bh = blockIdx.y;
    int b = bh >> 4, h = bh & 15, hk = h >> 1;
    int q0 = blockIdx.x << 6;
    int tid = threadIdx.x;
    int ty = tid >> 4, tx = tid & 15;

    const float4* Qg = (const float4*)(g_q + ((size_t)(b * NH + h) * S_ + q0) * HD);
    const float*  Kg = g_k + (size_t)(b * NKV + hk) * S_ * HD;
    const float*  Vg = g_v + (size_t)(b * NKV + hk) * S_ * HD;
    float m1h = m1[h], m2h = m2[h];

    for (int it = tid; it < 2048; it += 256) {
        int r = it >> 5, d4 = it & 31;
        float4 vq = Qg[r * 32 + d4];
        int base = (d4 * 4) * 68 + r;
        Qt[base]       = vq.x;
        Qt[base + 68]  = vq.y;
        Qt[base + 136] = vq.z;
        Qt[base + 204] = vq.w;
    }

    float mrow[4], lrow[4], O[4][8];
    #pragma unroll
    for (int i = 0; i < 4; i++) {
        mrow[i] = -3e38f; lrow[i] = 0.f;
        #pragma unroll
        for (int j = 0; j < 8; j++) O[i][j] = 0.f;
    }

    int nkt = (q0 >> 6) + 1;
    for (int kt = 0; kt < nkt; kt++) {
        int k0 = kt << 6;
        __syncthreads();
        const float4* Kg4 = (const float4*)(Kg + (size_t)k0 * HD);
        for (int it = tid; it < 2048; it += 256) {
            int r = it >> 5, d4 = it & 31;
            float4 vk = Kg4[r * 32 + d4];
            int base = (d4 * 4) * 68 + r;
            Kt[base]       = vk.x;
            Kt[base + 68]  = vk.y;
            Kt[base + 136] = vk.z;
            Kt[base + 204] = vk.w;
        }
        if (tid < 64) bk[tid] = m1h * g_delta[k0 + tid] + m2h * g_post[k0 + tid];
        __syncthreads();

        float S[4][4];
        #pragma unroll
        for (int i = 0; i < 4; i++)
            #pragma unroll
            for (int j = 0; j < 4; j++) S[i][j] = 0.f;
        #pragma unroll 4
        for (int d = 0; d < 128; d++) {
            float4 qa = *(const float4*)&Qt[d * 68 + (ty << 2)];
            float4 kb = *(const float4*)&Kt[d * 68 + (tx << 2)];
            float qr[4] = {qa.x, qa.y, qa.z, qa.w};
            float kr[4] = {kb.x, kb.y, kb.z, kb.w};
            #pragma unroll
            for (int i = 0; i < 4; i++)
                #pragma unroll
                for (int j = 0; j < 4; j++) S[i][j] += qr[i] * kr[j];
        }

        float mnew[4];
        #pragma unroll
        for (int i = 0; i < 4; i++) {
            int qg = q0 + (ty << 2) + i;
            mnew[i] = mrow[i];
            #pragma unroll
            for (int j = 0; j < 4; j++) {
                int kg = k0 + (tx << 2) + j;
                float vv = S[i][j] * SCALING + bk[(tx << 2) + j];
                vv = (kg <= qg) ? vv : -3e38f;
                S[i][j] = vv;
                mnew[i] = fmaxf(mnew[i], vv);
            }
        }
        #pragma unroll
        for (int i = 0; i < 4; i++)
            for (int o = 8; o; o >>= 1)
                mnew[i] = fmaxf(mnew[i], __shfl_xor_sync(0xffffffffu, mnew[i], o));
        #pragma unroll
        for (int i = 0; i < 4; i++) {
            float pr = 0.f;
            #pragma unroll
            for (int j = 0; j < 4; j++) {
                float p = __expf(S[i][j] - mnew[i]);
                Ps[((ty << 2) + i) * 68 + (tx << 2) + j] = p;
                pr += p;
            }
            for (int o = 8; o; o >>= 1) pr += __shfl_xor_sync(0xffffffffu, pr, o);
            float sc = __expf(mrow[i] - mnew[i]);
            lrow[i] = lrow[i] * sc + pr;
            mrow[i] = mnew[i];
            #pragma unroll
            for (int j = 0; j < 8; j++) O[i][j] *= sc;
        }
        __syncthreads();

        const float4* Vg4 = (const float4*)(Vg + (size_t)k0 * HD);
        float4* Vs4 = (float4*)Kt;
        for (int it = tid; it < 2048; it += 256) {
            int r = it >> 5, d4 = it & 31;
            Vs4[r * 33 + d4] = Vg4[r * 32 + d4];
        }
        __syncthreads();

        #pragma unroll 4
        for (int kk = 0; kk < 64; kk++) {
            float4 v0 = Vs4[kk * 33 + (tx << 1)];
            float4 v1 = Vs4[kk * 33 + (tx << 1) + 1];
            #pragma unroll
            for (int i = 0; i < 4; i++) {
                float p = Ps[((ty << 2) + i) * 68 + kk];
                O[i][0] += p * v0.x; O[i][1] += p * v0.y;
                O[i][2] += p * v0.z; O[i][3] += p * v0.w;
                O[i][4] += p * v1.x; O[i][5] += p * v1.y;
                O[i][6] += p * v1.z; O[i][7] += p * v1.w;
            }
        }
    }

    #pragma unroll
    for (int i = 0; i < 4; i++) {
        int qg = q0 + (ty << 2) + i;
        float inv = 1.f / lrow[i];
        float* op = g_ao + (size_t)(b * S_ + qg) * (NH * HD) + h * HD + (tx << 3);
        #pragma unroll
        for (int j = 0; j < 8; j++) op[j] = O[i][j] * inv;
    }
}

// ---------------- launch ----------------
extern "C" void kernel_launch(void* const* d_in, const int* in_sizes, int n_in,
                              void* d_out, int out_size) {
    const float* hidden = (const float*)d_in[0];
    const float* cosb   = (const float*)d_in[1];
    const float* sinb   = (const float*)d_in[2];
    const float* prior  = (const float*)d_in[4];
    const float* m1     = (const float*)d_in[5];
    const float* m2     = (const float*)d_in[6];
    const float* Wq     = (const float*)d_in[7];
    const float* Wk     = (const float*)d_in[8];
    const float* Wv     = (const float*)d_in[9];
    const float* Wo     = (const float*)d_in[10];
    const float* qw     = (const float*)d_in[11];
    const float* kw     = (const float*)d_in[12];
    float* out = (float*)d_out;

    float *qraw, *kraw, *vraw, *ao;
    __nv_bfloat16 *ahi, *alo, *aoh, *aol;
    __nv_bfloat16 *wqh, *wql, *wkh, *wkl, *wvh, *wvl, *woh, *wol;
    cudaGetSymbolAddress((void**)&qraw, g_qraw);
    cudaGetSymbolAddress((void**)&kraw, g_kraw);
    cudaGetSymbolAddress((void**)&vraw, g_vraw);
    cudaGetSymbolAddress((void**)&ao,   g_ao);
    cudaGetSymbolAddress((void**)&ahi,  g_ahi);
    cudaGetSymbolAddress((void**)&alo,  g_alo);
    cudaGetSymbolAddress((void**)&aoh,  g_aoh);
    cudaGetSymbolAddress((void**)&aol,  g_aol);
    cudaGetSymbolAddress((void**)&wqh,  g_wqt_h);
    cudaGetSymbolAddress((void**)&wql,  g_wqt_l);
    cudaGetSymbolAddress((void**)&wkh,  g_wkt_h);
    cudaGetSymbolAddress((void**)&wkl,  g_wkt_l);
    cudaGetSymbolAddress((void**)&wvh,  g_wvt_h);
    cudaGetSymbolAddress((void**)&wvl,  g_wvt_l);
    cudaGetSymbolAddress((void**)&woh,  g_wot_h);
    cudaGetSymbolAddress((void**)&wol,  g_wot_l);

    const int ATTN_SMEM = 21824 * 4;
    cudaFuncSetAttribute(attn_kernel, cudaFuncAttributeMaxDynamicSharedMemorySize, ATTN_SMEM);
    cudaFuncSetAttribute(gemm_mma_kernel, cudaFuncAttributeMaxDynamicSharedMemorySize, GEMM_SMEM);

    prep_kernel<<<1, 256>>>(prior);

    // split activations + weights into bf16 hi/lo (weights transposed to [N,K])
    split_kernel<<<(MTOK * HID) / 1024, 256>>>(hidden, ahi, alo);
    tsplit_kernel<<<dim3(64, 64), 256>>>(Wq, wqh, wql, 2048, 2048);
    tsplit_kernel<<<dim3(32, 64), 256>>>(Wk, wkh, wkl, 2048, 1024);
    tsplit_kernel<<<dim3(32, 64), 256>>>(Wv, wvh, wvl, 2048, 1024);
    tsplit_kernel<<<dim3(64, 64), 256>>>(Wo, woh, wol, 2048, 2048);

    gemm_mma_kernel<<<dim3(16, 32), 256, GEMM_SMEM>>>(ahi, alo, wqh, wql, qraw, 2048, 2048);
    gemm_mma_kernel<<<dim3(8, 32),  256, GEMM_SMEM>>>(ahi, alo, wkh, wkl, kraw, 1024, 2048);
    gemm_mma_kernel<<<dim3(8, 32),  256, GEMM_SMEM>>>(ahi, alo, wvh, wvl, vraw, 1024, 2048);

    transform_kernel<<<dim3(MTOK, NH + 2 * NKV), 128>>>(cosb, sinb, qw, kw);

    attn_kernel<<<dim3(S_ / 64, B_ * NH), 256, ATTN_SMEM>>>(m1, m2);

    split_kernel<<<(MTOK * HID) / 1024, 256>>>(ao, aoh, aol);
    gemm_mma_kernel<<<dim3(16, 32), 256, GEMM_SMEM>>>(aoh, aol, woh, wol, out, 2048, 2048);
}

// round 8
// speedup vs baseline: 2.0238x; 1.2357x over previous
#include <cuda_runtime.h>
#include <cuda_bf16.h>
#include <math.h>
#include <stdint.h>

#define B_   2
#define S_   2048
#define HID  2048
#define NH   16
#define NKV  8
#define HD   128
#define MTOK (B_ * S_)          // 4096
#define SCALING 0.08838834764831845f

// ---------------- scratch ----------------
__device__ float g_qraw[MTOK * NH * HD];
__device__ float g_kraw[MTOK * NKV * HD];
__device__ float g_vraw[MTOK * NKV * HD];
__device__ float g_q[MTOK * NH * HD];
__device__ float g_k[MTOK * NKV * HD];
__device__ float g_v[MTOK * NKV * HD];
__device__ float g_ao[MTOK * NH * HD];
__device__ float g_delta[S_];
__device__ float g_post[S_];
__device__ float g_gamma[S_];
__device__ float g_eta[S_];

__device__ __nv_bfloat16 g_ahi[MTOK * HID];
__device__ __nv_bfloat16 g_alo[MTOK * HID];
__device__ __nv_bfloat16 g_aoh[MTOK * HID];
__device__ __nv_bfloat16 g_aol[MTOK * HID];
__device__ __nv_bfloat16 g_wqt_h[HID * HID];
__device__ __nv_bfloat16 g_wqt_l[HID * HID];
__device__ __nv_bfloat16 g_wkt_h[NKV * HD * HID];
__device__ __nv_bfloat16 g_wkt_l[NKV * HD * HID];
__device__ __nv_bfloat16 g_wvt_h[NKV * HD * HID];
__device__ __nv_bfloat16 g_wvt_l[NKV * HD * HID];
__device__ __nv_bfloat16 g_wot_h[HID * HID];
__device__ __nv_bfloat16 g_wot_l[HID * HID];

__device__ __forceinline__ uint32_t smem_u32(const void* p) {
    uint32_t a;
    asm("{ .reg .u64 t; cvta.to.shared.u64 t, %1; cvt.u32.u64 %0, t; }" : "=r"(a) : "l"(p));
    return a;
}
__device__ __forceinline__ uint32_t pack_bf2(float x, float y) {
    __nv_bfloat162 t(__float2bfloat16(x), __float2bfloat16(y));
    return *(uint32_t*)&t;
}
__device__ __forceinline__ float bf_hi_f(float x) {
    return __bfloat162float(__float2bfloat16(x));
}

#define MMA_BF16(d, a, b) \
    asm volatile("mma.sync.aligned.m16n8k16.row.col.f32.bf16.bf16.f32 " \
                 "{%0,%1,%2,%3}, {%4,%5,%6,%7}, {%8,%9}, {%0,%1,%2,%3};" \
                 : "+f"((d)[0]), "+f"((d)[1]), "+f"((d)[2]), "+f"((d)[3]) \
                 : "r"((a)[0]), "r"((a)[1]), "r"((a)[2]), "r"((a)[3]), \
                   "r"((b)[0]), "r"((b)[1]))
#define LDSM_X4(r, addr) \
    asm volatile("ldmatrix.sync.aligned.m8n8.x4.shared.b16 {%0,%1,%2,%3}, [%4];" \
                 : "=r"((r)[0]), "=r"((r)[1]), "=r"((r)[2]), "=r"((r)[3]) : "r"(addr))
#define LDSM_X2(r, addr) \
    asm volatile("ldmatrix.sync.aligned.m8n8.x2.shared.b16 {%0,%1}, [%2];" \
                 : "=r"((r)[0]), "=r"((r)[1]) : "r"(addr))

// ---------------- prep ----------------
__global__ __launch_bounds__(256) void prep_kernel(const float* __restrict__ prior) {
    __shared__ float red[8];
    int t = threadIdx.x;
    float s = 0.f;
    for (int i = t; i < S_; i += 256) s += prior[i];
    for (int o = 16; o; o >>= 1) s += __shfl_down_sync(0xffffffffu, s, o);
    if ((t & 31) == 0) red[t >> 5] = s;
    __syncthreads();
    float tot = 0.f;
    #pragma unroll
    for (int i = 0; i < 8; i++) tot += red[i];
    float inv = 1.f / tot;
    for (int i = t; i < S_; i += 256) {
        float p = prior[i] * inv;
        float c = p * (float)S_ - 1.f;
        float g = 1.f + 0.5f * c;
        g_gamma[i] = fminf(fmaxf(g, 0.8f), 1.25f);
        g_eta[i]   = fminf(fmaxf(g, 0.9f), 1.1f);
        g_delta[i] = fminf(fmaxf(logf(p + 1e-8f), -2.f), 2.f);
        g_post[i]  = 0.5f * logf(p * (float)S_);
    }
}

// ---------------- fp32 -> (hi, lo) bf16 split ----------------
__global__ __launch_bounds__(256) void split_kernel(const float* __restrict__ x,
                                                    __nv_bfloat16* __restrict__ hi,
                                                    __nv_bfloat16* __restrict__ lo) {
    int i = (blockIdx.x * 256 + threadIdx.x) * 4;
    float4 v = *(const float4*)(x + i);
    float a0 = v.x, a1 = v.y, a2 = v.z, a3 = v.w;
    __nv_bfloat16 h0 = __float2bfloat16(a0), h1 = __float2bfloat16(a1);
    __nv_bfloat16 h2 = __float2bfloat16(a2), h3 = __float2bfloat16(a3);
    __nv_bfloat16 l0 = __float2bfloat16(a0 - __bfloat162float(h0));
    __nv_bfloat16 l1 = __float2bfloat16(a1 - __bfloat162float(h1));
    __nv_bfloat16 l2 = __float2bfloat16(a2 - __bfloat162float(h2));
    __nv_bfloat16 l3 = __float2bfloat16(a3 - __bfloat162float(h3));
    *(__nv_bfloat162*)(hi + i)     = __nv_bfloat162(h0, h1);
    *(__nv_bfloat162*)(hi + i + 2) = __nv_bfloat162(h2, h3);
    *(__nv_bfloat162*)(lo + i)     = __nv_bfloat162(l0, l1);
    *(__nv_bfloat162*)(lo + i + 2) = __nv_bfloat162(l2, l3);
}

// ---------------- transpose + split ----------------
__global__ __launch_bounds__(256) void tsplit_kernel(const float* __restrict__ W,
                                                     __nv_bfloat16* __restrict__ Th,
                                                     __nv_bfloat16* __restrict__ Tl,
                                                     int K, int N) {
    __shared__ float ts[32][33];
    int tx = threadIdx.x & 31, ty = threadIdx.x >> 5;
    int k0 = blockIdx.y << 5, n0 = blockIdx.x << 5;
    #pragma unroll
    for (int i = 0; i < 4; i++)
        ts[ty + 8 * i][tx] = W[(size_t)(k0 + ty + 8 * i) * N + n0 + tx];
    __syncthreads();
    #pragma unroll
    for (int i = 0; i < 4; i++) {
        int nl = ty + 8 * i;
        float x = ts[tx][nl];
        __nv_bfloat16 h = __float2bfloat16(x);
        __nv_bfloat16 l = __float2bfloat16(x - __bfloat162float(h));
        size_t o = (size_t)(n0 + nl) * K + k0 + tx;
        Th[o] = h;
        Tl[o] = l;
    }
}

// ---------------- bf16 split GEMM via mma.sync (unchanged, proven in R7) ----------------
#define GEMM_SMEM 81920
__global__ __launch_bounds__(256) void gemm_mma_kernel(
    const __nv_bfloat16* __restrict__ Ah, const __nv_bfloat16* __restrict__ Al,
    const __nv_bfloat16* __restrict__ Bh, const __nv_bfloat16* __restrict__ Bl,
    float* __restrict__ C, int N, int K)
{
    extern __shared__ char gsm[];
    uint32_t sb = smem_u32(gsm);
    int tid = threadIdx.x, w = tid >> 5, lane = tid & 31;
    int wm = (w >> 2) * 64, wn = (w & 3) * 32;
    int row0 = blockIdx.y << 7, col0 = blockIdx.x << 7;

    const __nv_bfloat16* gp[4] = {Ah, Al, Bh, Bl};

    auto stage_load = [&](int kc, int s) {
        uint32_t base = sb + (uint32_t)s * 40960u;
        #pragma unroll
        for (int i = 0; i < 8; i++) {
            int it = i * 256 + tid;
            int t  = it >> 9;
            int r  = (it >> 2) & 127;
            int j  = it & 3;
            const __nv_bfloat16* g = gp[t] + (size_t)((t < 2 ? row0 : col0) + r) * K + kc + j * 8;
            uint32_t dst = base + (uint32_t)t * 10240u + (uint32_t)r * 80u + (uint32_t)j * 16u;
            asm volatile("cp.async.cg.shared.global [%0], [%1], 16;" :: "r"(dst), "l"(g));
        }
        asm volatile("cp.async.commit_group;");
    };

    float acc[4][4][4];
    #pragma unroll
    for (int a = 0; a < 4; a++)
        #pragma unroll
        for (int b = 0; b < 4; b++)
            #pragma unroll
            for (int c = 0; c < 4; c++) acc[a][b][c] = 0.f;

    stage_load(0, 0);

    for (int kc = 0; kc < K; kc += 32) {
        int s = (kc >> 5) & 1;
        if (kc + 32 < K) {
            stage_load(kc + 32, s ^ 1);
            asm volatile("cp.async.wait_group 1;");
        } else {
            asm volatile("cp.async.wait_group 0;");
        }
        __syncthreads();

        uint32_t base = sb + (uint32_t)s * 40960u;
        uint32_t ahB = base, alB = base + 10240u, bhB = base + 20480u, blB = base + 30720u;

        #pragma unroll
        for (int ks = 0; ks < 32; ks += 16) {
            uint32_t aoff = (uint32_t)((lane & 15)) * 80u + (uint32_t)(ks + ((lane >> 4) << 3)) * 2u;
            uint32_t boff = (uint32_t)((lane & 7)) * 80u + (uint32_t)(ks + ((lane >> 3) & 1) * 8) * 2u;

            uint32_t ah[4][4], al[4][4], bh[4][2], bl[4][2];
            #pragma unroll
            for (int mt = 0; mt < 4; mt++) {
                uint32_t ra = (uint32_t)(wm + mt * 16) * 80u + aoff;
                LDSM_X4(ah[mt], ahB + ra);
                LDSM_X4(al[mt], alB + ra);
            }
            #pragma unroll
            for (int nt = 0; nt < 4; nt++) {
                uint32_t rb = (uint32_t)(wn + nt * 8) * 80u + boff;
                LDSM_X2(bh[nt], bhB + rb);
                LDSM_X2(bl[nt], blB + rb);
            }
            #pragma unroll
            for (int mt = 0; mt < 4; mt++) {
                #pragma unroll
                for (int nt = 0; nt < 4; nt++) {
                    MMA_BF16(acc[mt][nt], ah[mt], bh[nt]);
                    MMA_BF16(acc[mt][nt], ah[mt], bl[nt]);
                    MMA_BF16(acc[mt][nt], al[mt], bh[nt]);
                }
            }
        }
        __syncthreads();
    }

    int er = lane >> 2, ec = (lane & 3) << 1;
    #pragma unroll
    for (int mt = 0; mt < 4; mt++) {
        #pragma unroll
        for (int nt = 0; nt < 4; nt++) {
            float* Cp = C + (size_t)(row0 + wm + mt * 16 + er) * N + col0 + wn + nt * 8 + ec;
            *(float2*)Cp           = make_float2(acc[mt][nt][0], acc[mt][nt][1]);
            *(float2*)(Cp + 8 * N) = make_float2(acc[mt][nt][2], acc[mt][nt][3]);
        }
    }
}

// ---------------- RMSnorm + RoPE + gamma/eta + transpose ----------------
__global__ __launch_bounds__(128) void transform_kernel(const float* __restrict__ cosb,
                                                        const float* __restrict__ sinb,
                                                        const float* __restrict__ qw,
                                                        const float* __restrict__ kw) {
    int m = blockIdx.x;
    int z = blockIdx.y;
    int d = threadIdx.x;
    int b = m >> 11, s = m & 2047;

    __shared__ float sh[HD];
    __shared__ float red[4];

    if (z >= NH + NKV) {
        int h = z - NH - NKV;
        float x = g_vraw[(size_t)m * (NKV * HD) + h * HD + d];
        g_v[((size_t)(b * NKV + h) * S_ + s) * HD + d] = x * g_eta[s];
        return;
    }
    int mode_q = (z < NH);
    int h = mode_q ? z : (z - NH);
    const float* src = mode_q ? (g_qraw + (size_t)m * (NH * HD) + h * HD)
                              : (g_kraw + (size_t)m * (NKV * HD) + h * HD);
    float x = src[d];
    sh[d] = x;
    float v2 = x * x;
    for (int o = 16; o; o >>= 1) v2 += __shfl_down_sync(0xffffffffu, v2, o);
    if ((d & 31) == 0) red[d >> 5] = v2;
    __syncthreads();
    float sum = red[0] + red[1] + red[2] + red[3];
    float rsq = rsqrtf(sum * (1.f / 128.f) + 1e-6f);
    const float* wn = mode_q ? qw : kw;
    float val = x * rsq * wn[d];
    float pv  = sh[d ^ 64] * rsq * wn[d ^ 64];
    float rot = (d < 64) ? -pv : pv;
    size_t ci = (size_t)m * HD + d;
    float o = val * cosb[ci] + rot * sinb[ci];
    if (mode_q)
        g_q[((size_t)(b * NH + h) * S_ + s) * HD + d] = o;
    else
        g_k[((size_t)(b * NKV + h) * S_ + s) * HD + d] = o * g_gamma[s];
}

// ---------------- tensor-core flash attention ----------------
// BQ=64, BK=32, 128 threads (4 warps, 16 q-rows each). Split-bf16 both GEMMs.
// smem: Qh 64x272, Ql, Kh 32x272, Kl, Vth 128x80, Vtl, bias 32 floats.
#define AQ_STRIDE 272
#define AV_STRIDE 80
#define A_QH 0
#define A_QL 17408
#define A_KH 34816
#define A_KL 43520
#define A_VH 52224
#define A_VL 62464
#define A_BS 72704
#define ATTN_SMEM 72832
__global__ __launch_bounds__(128) void attn_mma_kernel(const float* __restrict__ m1,
                                                       const float* __restrict__ m2) {
    extern __shared__ char asmem[];
    uint32_t sb = smem_u32(asmem);
    float* biasS = (float*)(asmem + A_BS);

    int bh = blockIdx.y;
    int b = bh >> 4, h = bh & 15, hk = h >> 1;
    int q0 = blockIdx.x << 6;
    int tid = threadIdx.x, w = tid >> 5, lane = tid & 31;
    int r = lane >> 2;                     // 0..7
    int rowA = q0 + w * 16 + r;            // global q row (thread's row a)
    int rowB = rowA + 8;

    const float4* Qg4 = (const float4*)(g_q + ((size_t)(b * NH + h) * S_ + q0) * HD);
    const float*  Kg  = g_k + (size_t)(b * NKV + hk) * S_ * HD;
    const float*  Vg  = g_v + (size_t)(b * NKV + hk) * S_ * HD;
    float m1h = m1[h], m2h = m2[h];

    // ---- stage Q (scaled by SCALING, split hi/lo) ----
    for (int it = tid; it < 2048; it += 128) {
        int rr = it >> 5, c4 = it & 31;
        float4 v = Qg4[rr * 32 + c4];
        v.x *= SCALING; v.y *= SCALING; v.z *= SCALING; v.w *= SCALING;
        uint32_t off = rr * AQ_STRIDE + c4 * 8;
        *(uint32_t*)(asmem + A_QH + off)     = pack_bf2(v.x, v.y);
        *(uint32_t*)(asmem + A_QH + off + 4) = pack_bf2(v.z, v.w);
        *(uint32_t*)(asmem + A_QL + off)     = pack_bf2(v.x - bf_hi_f(v.x), v.y - bf_hi_f(v.y));
        *(uint32_t*)(asmem + A_QL + off + 4) = pack_bf2(v.z - bf_hi_f(v.z), v.w - bf_hi_f(v.w));
    }

    float O[16][4];
    #pragma unroll
    for (int nt = 0; nt < 16; nt++)
        #pragma unroll
        for (int j = 0; j < 4; j++) O[nt][j] = 0.f;
    float mA = -3e38f, mB = -3e38f, lA = 0.f, lB = 0.f;

    int nkt = (q0 >> 5) + 2;
    for (int kt = 0; kt < nkt; kt++) {
        int k0 = kt << 5;
        __syncthreads();
        // ---- stage K tile (32x128 -> hi/lo) ----
        const float4* Kg4 = (const float4*)(Kg + (size_t)k0 * HD);
        for (int it = tid; it < 1024; it += 128) {
            int rr = it >> 5, c4 = it & 31;
            float4 v = Kg4[rr * 32 + c4];
            uint32_t off = rr * AQ_STRIDE + c4 * 8;
            *(uint32_t*)(asmem + A_KH + off)     = pack_bf2(v.x, v.y);
            *(uint32_t*)(asmem + A_KH + off + 4) = pack_bf2(v.z, v.w);
            *(uint32_t*)(asmem + A_KL + off)     = pack_bf2(v.x - bf_hi_f(v.x), v.y - bf_hi_f(v.y));
            *(uint32_t*)(asmem + A_KL + off + 4) = pack_bf2(v.z - bf_hi_f(v.z), v.w - bf_hi_f(v.w));
        }
        // ---- stage V tile transposed (Vt[d][s] hi/lo) ----
        const float4* Vg4 = (const float4*)(Vg + (size_t)k0 * HD);
        for (int it = tid; it < 1024; it += 128) {
            int ss = it >> 5, c4 = it & 31;
            float4 v = Vg4[ss * 32 + c4];
            float vv[4] = {v.x, v.y, v.z, v.w};
            #pragma unroll
            for (int jj = 0; jj < 4; jj++) {
                int d = c4 * 4 + jj;
                float x = vv[jj];
                __nv_bfloat16 hx = __float2bfloat16(x);
                *(__nv_bfloat16*)(asmem + A_VH + d * AV_STRIDE + ss * 2) = hx;
                *(__nv_bfloat16*)(asmem + A_VL + d * AV_STRIDE + ss * 2) =
                    __float2bfloat16(x - __bfloat162float(hx));
            }
        }
        if (tid < 32) biasS[tid] = m1h * g_delta[k0 + tid] + m2h * g_post[k0 + tid];
        __syncthreads();

        // ---- S = Q*K^T (4 n-tiles of 8 cols) ----
        float S[4][4];
        #pragma unroll
        for (int nt = 0; nt < 4; nt++)
            #pragma unroll
            for (int j = 0; j < 4; j++) S[nt][j] = 0.f;

        uint32_t aoff = (uint32_t)(w * 16 + (lane & 15)) * AQ_STRIDE +
                        (uint32_t)(((lane >> 4) << 3)) * 2u;
        uint32_t boff = (uint32_t)((lane & 7)) * AQ_STRIDE +
                        (uint32_t)(((lane >> 3) & 1) * 8) * 2u;
        #pragma unroll
        for (int ks = 0; ks < 8; ks++) {
            uint32_t ka = aoff + ks * 32u;     // 16 bf16 = 32 B per k-step
            uint32_t qh[4], ql[4];
            LDSM_X4(qh, sb + A_QH + ka);
            LDSM_X4(ql, sb + A_QL + ka);
            #pragma unroll
            for (int nt = 0; nt < 4; nt++) {
                uint32_t kb = boff + (uint32_t)(nt * 8) * AQ_STRIDE + ks * 32u;
                uint32_t bh2[2], bl2[2];
                LDSM_X2(bh2, sb + A_KH + kb);
                LDSM_X2(bl2, sb + A_KL + kb);
                MMA_BF16(S[nt], qh, bh2);
                MMA_BF16(S[nt], qh, bl2);
                MMA_BF16(S[nt], ql, bh2);
            }
        }

        // ---- bias + causal mask ----
        int cbase = 2 * (lane & 3);
        bool need_mask = (k0 + 31 > q0);     // only diagonal tiles
        #pragma unroll
        for (int nt = 0; nt < 4; nt++) {
            int c0l = nt * 8 + cbase;
            float b0 = biasS[c0l], b1 = biasS[c0l + 1];
            S[nt][0] += b0; S[nt][1] += b1;
            S[nt][2] += b0; S[nt][3] += b1;
            if (need_mask) {
                int c0g = k0 + c0l;
                if (c0g > rowA)     S[nt][0] = -3e38f;
                if (c0g + 1 > rowA) S[nt][1] = -3e38f;
                if (c0g > rowB)     S[nt][2] = -3e38f;
                if (c0g + 1 > rowB) S[nt][3] = -3e38f;
            }
        }

        // ---- online softmax (rows a, b) ----
        float cmA = -3e38f, cmB = -3e38f;
        #pragma unroll
        for (int nt = 0; nt < 4; nt++) {
            cmA = fmaxf(cmA, fmaxf(S[nt][0], S[nt][1]));
            cmB = fmaxf(cmB, fmaxf(S[nt][2], S[nt][3]));
        }
        cmA = fmaxf(cmA, __shfl_xor_sync(0xffffffffu, cmA, 1));
        cmA = fmaxf(cmA, __shfl_xor_sync(0xffffffffu, cmA, 2));
        cmB = fmaxf(cmB, __shfl_xor_sync(0xffffffffu, cmB, 1));
        cmB = fmaxf(cmB, __shfl_xor_sync(0xffffffffu, cmB, 2));
        float mnA = fmaxf(mA, cmA), mnB = fmaxf(mB, cmB);
        float sumA = 0.f, sumB = 0.f;
        #pragma unroll
        for (int nt = 0; nt < 4; nt++) {
            S[nt][0] = __expf(S[nt][0] - mnA);
            S[nt][1] = __expf(S[nt][1] - mnA);
            S[nt][2] = __expf(S[nt][2] - mnB);
            S[nt][3] = __expf(S[nt][3] - mnB);
            sumA += S[nt][0] + S[nt][1];
            sumB += S[nt][2] + S[nt][3];
        }
        sumA += __shfl_xor_sync(0xffffffffu, sumA, 1);
        sumA += __shfl_xor_sync(0xffffffffu, sumA, 2);
        sumB += __shfl_xor_sync(0xffffffffu, sumB, 1);
        sumB += __shfl_xor_sync(0xffffffffu, sumB, 2);
        float scA = __expf(mA - mnA), scB = __expf(mB - mnB);
        lA = lA * scA + sumA; lB = lB * scB + sumB;
        mA = mnA; mB = mnB;
        #pragma unroll
        for (int nt = 0; nt < 16; nt++) {
            O[nt][0] *= scA; O[nt][1] *= scA;
            O[nt][2] *= scB; O[nt][3] *= scB;
        }

        // ---- P fragments (hi/lo) from S accum pairs; PV over d ----
        uint32_t vboff = (uint32_t)((lane & 7)) * AV_STRIDE +
                         (uint32_t)(((lane >> 3) & 1) * 8) * 2u;
        #pragma unroll
        for (int sk = 0; sk < 2; sk++) {
            float* t0 = S[2 * sk];
            float* t1 = S[2 * sk + 1];
            uint32_t ph[4], pl[4];
            ph[0] = pack_bf2(t0[0], t0[1]);
            ph[1] = pack_bf2(t0[2], t0[3]);
            ph[2] = pack_bf2(t1[0], t1[1]);
            ph[3] = pack_bf2(t1[2], t1[3]);
            pl[0] = pack_bf2(t0[0] - bf_hi_f(t0[0]), t0[1] - bf_hi_f(t0[1]));
            pl[1] = pack_bf2(t0[2] - bf_hi_f(t0[2]), t0[3] - bf_hi_f(t0[3]));
            pl[2] = pack_bf2(t1[0] - bf_hi_f(t1[0]), t1[1] - bf_hi_f(t1[1]));
            pl[3] = pack_bf2(t1[2] - bf_hi_f(t1[2]), t1[3] - bf_hi_f(t1[3]));
            #pragma unroll
            for (int nt = 0; nt < 16; nt++) {
                uint32_t vb = vboff + (uint32_t)(nt * 8) * AV_STRIDE + (uint32_t)(sk * 16) * 2u;
                uint32_t vh2[2], vl2[2];
                LDSM_X2(vh2, sb + A_VH + vb);
                LDSM_X2(vl2, sb + A_VL + vb);
                MMA_BF16(O[nt], ph, vh2);
                MMA_BF16(O[nt], ph, vl2);
                MMA_BF16(O[nt], pl, vh2);
            }
        }
    }

    // ---- epilogue ----
    float invA = 1.f / lA, invB = 1.f / lB;
    float* oA = g_ao + (size_t)(b * S_ + rowA) * (NH * HD) + h * HD;
    float* oB = g_ao + (size_t)(b * S_ + rowB) * (NH * HD) + h * HD;
    int ec = 2 * (lane & 3);
    #pragma unroll
    for (int nt = 0; nt < 16; nt++) {
        int c = nt * 8 + ec;
        *(float2*)(oA + c) = make_float2(O[nt][0] * invA, O[nt][1] * invA);
        *(float2*)(oB + c) = make_float2(O[nt][2] * invB, O[nt][3] * invB);
    }
}

// ---------------- launch ----------------
extern "C" void kernel_launch(void* const* d_in, const int* in_sizes, int n_in,
                              void* d_out, int out_size) {
    const float* hidden = (const float*)d_in[0];
    const float* cosb   = (const float*)d_in[1];
    const float* sinb   = (const float*)d_in[2];
    const float* prior  = (const float*)d_in[4];
    const float* m1     = (const float*)d_in[5];
    const float* m2     = (const float*)d_in[6];
    const float* Wq     = (const float*)d_in[7];
    const float* Wk     = (const float*)d_in[8];
    const float* Wv     = (const float*)d_in[9];
    const float* Wo     = (const float*)d_in[10];
    const float* qw     = (const float*)d_in[11];
    const float* kw     = (const float*)d_in[12];
    float* out = (float*)d_out;

    float *qraw, *kraw, *vraw, *ao;
    __nv_bfloat16 *ahi, *alo, *aoh, *aol;
    __nv_bfloat16 *wqh, *wql, *wkh, *wkl, *wvh, *wvl, *woh, *wol;
    cudaGetSymbolAddress((void**)&qraw, g_qraw);
    cudaGetSymbolAddress((void**)&kraw, g_kraw);
    cudaGetSymbolAddress((void**)&vraw, g_vraw);
    cudaGetSymbolAddress((void**)&ao,   g_ao);
    cudaGetSymbolAddress((void**)&ahi,  g_ahi);
    cudaGetSymbolAddress((void**)&alo,  g_alo);
    cudaGetSymbolAddress((void**)&aoh,  g_aoh);
    cudaGetSymbolAddress((void**)&aol,  g_aol);
    cudaGetSymbolAddress((void**)&wqh,  g_wqt_h);
    cudaGetSymbolAddress((void**)&wql,  g_wqt_l);
    cudaGetSymbolAddress((void**)&wkh,  g_wkt_h);
    cudaGetSymbolAddress((void**)&wkl,  g_wkt_l);
    cudaGetSymbolAddress((void**)&wvh,  g_wvt_h);
    cudaGetSymbolAddress((void**)&wvl,  g_wvt_l);
    cudaGetSymbolAddress((void**)&woh,  g_wot_h);
    cudaGetSymbolAddress((void**)&wol,  g_wot_l);

    cudaFuncSetAttribute(attn_mma_kernel, cudaFuncAttributeMaxDynamicSharedMemorySize, ATTN_SMEM);
    cudaFuncSetAttribute(gemm_mma_kernel, cudaFuncAttributeMaxDynamicSharedMemorySize, GEMM_SMEM);

    prep_kernel<<<1, 256>>>(prior);

    split_kernel<<<(MTOK * HID) / 1024, 256>>>(hidden, ahi, alo);
    tsplit_kernel<<<dim3(64, 64), 256>>>(Wq, wqh, wql, 2048, 2048);
    tsplit_kernel<<<dim3(32, 64), 256>>>(Wk, wkh, wkl, 2048, 1024);
    tsplit_kernel<<<dim3(32, 64), 256>>>(Wv, wvh, wvl, 2048, 1024);
    tsplit_kernel<<<dim3(64, 64), 256>>>(Wo, woh, wol, 2048, 2048);

    gemm_mma_kernel<<<dim3(16, 32), 256, GEMM_SMEM>>>(ahi, alo, wqh, wql, qraw, 2048, 2048);
    gemm_mma_kernel<<<dim3(8, 32),  256, GEMM_SMEM>>>(ahi, alo, wkh, wkl, kraw, 1024, 2048);
    gemm_mma_kernel<<<dim3(8, 32),  256, GEMM_SMEM>>>(ahi, alo, wvh, wvl, vraw, 1024, 2048);

    transform_kernel<<<dim3(MTOK, NH + 2 * NKV), 128>>>(cosb, sinb, qw, kw);

    attn_mma_kernel<<<dim3(S_ / 64, B_ * NH), 128, ATTN_SMEM>>>(m1, m2);

    split_kernel<<<(MTOK * HID) / 1024, 256>>>(ao, aoh, aol);
    gemm_mma_kernel<<<dim3(16, 32), 256, GEMM_SMEM>>>(aoh, aol, woh, wol, out, 2048, 2048);
}

// round 10
// speedup vs baseline: 3.0016x; 1.4832x over previous
#include <cuda_runtime.h>
#include <cuda_bf16.h>
#include <math.h>
#include <stdint.h>

#define B_   2
#define S_   2048
#define HID  2048
#define NH   16
#define NKV  8
#define HD   128
#define MTOK (B_ * S_)          // 4096
#define SCALING 0.08838834764831845f

// ---------------- scratch ----------------
__device__ float g_qraw[MTOK * NH * HD];
__device__ float g_kraw[MTOK * NKV * HD];
__device__ float g_vraw[MTOK * NKV * HD];
__device__ float g_ao[MTOK * NH * HD];
__device__ float g_delta[S_];
__device__ float g_post[S_];
__device__ float g_gamma[S_];
__device__ float g_eta[S_];

// attention operands (pre-converted)
__device__ __nv_bfloat16 g_qh[MTOK * NH * HD];   // scaled by SCALING, hi
__device__ __nv_bfloat16 g_ql[MTOK * NH * HD];   // lo
__device__ __nv_bfloat16 g_kh[MTOK * NKV * HD];  // gamma-scaled, hi
__device__ __nv_bfloat16 g_kl[MTOK * NKV * HD];
__device__ __nv_bfloat16 g_vth[B_ * NKV * HD * S_];  // eta-scaled, transposed [b][kv][d][s], hi
__device__ __nv_bfloat16 g_vtl[B_ * NKV * HD * S_];

// split-bf16 GEMM operands
__device__ __nv_bfloat16 g_ahi[MTOK * HID];
__device__ __nv_bfloat16 g_alo[MTOK * HID];
__device__ __nv_bfloat16 g_aoh[MTOK * HID];
__device__ __nv_bfloat16 g_aol[MTOK * HID];
__device__ __nv_bfloat16 g_wqt_h[HID * HID];
__device__ __nv_bfloat16 g_wqt_l[HID * HID];
__device__ __nv_bfloat16 g_wkt_h[NKV * HD * HID];
__device__ __nv_bfloat16 g_wkt_l[NKV * HD * HID];
__device__ __nv_bfloat16 g_wvt_h[NKV * HD * HID];
__device__ __nv_bfloat16 g_wvt_l[NKV * HD * HID];
__device__ __nv_bfloat16 g_wot_h[HID * HID];
__device__ __nv_bfloat16 g_wot_l[HID * HID];

__device__ __forceinline__ uint32_t smem_u32(const void* p) {
    uint32_t a;
    asm("{ .reg .u64 t; cvta.to.shared.u64 t, %1; cvt.u32.u64 %0, t; }" : "=r"(a) : "l"(p));
    return a;
}
__device__ __forceinline__ uint32_t pack_bf2(float x, float y) {
    __nv_bfloat162 t(__float2bfloat16(x), __float2bfloat16(y));
    return *(uint32_t*)&t;
}
__device__ __forceinline__ float bf_hi_f(float x) {
    return __bfloat162float(__float2bfloat16(x));
}

#define MMA_BF16(d, a, b) \
    asm volatile("mma.sync.aligned.m16n8k16.row.col.f32.bf16.bf16.f32 " \
                 "{%0,%1,%2,%3}, {%4,%5,%6,%7}, {%8,%9}, {%0,%1,%2,%3};" \
                 : "+f"((d)[0]), "+f"((d)[1]), "+f"((d)[2]), "+f"((d)[3]) \
                 : "r"((a)[0]), "r"((a)[1]), "r"((a)[2]), "r"((a)[3]), \
                   "r"((b)[0]), "r"((b)[1]))
#define LDSM_X4(r, addr) \
    asm volatile("ldmatrix.sync.aligned.m8n8.x4.shared.b16 {%0,%1,%2,%3}, [%4];" \
                 : "=r"((r)[0]), "=r"((r)[1]), "=r"((r)[2]), "=r"((r)[3]) : "r"(addr))
#define LDSM_X2(r, addr) \
    asm volatile("ldmatrix.sync.aligned.m8n8.x2.shared.b16 {%0,%1}, [%2];" \
                 : "=r"((r)[0]), "=r"((r)[1]) : "r"(addr))
#define CP16(dst, src) \
    asm volatile("cp.async.cg.shared.global [%0], [%1], 16;" :: "r"(dst), "l"(src))

// ---------------- prep ----------------
__global__ __launch_bounds__(256) void prep_kernel(const float* __restrict__ prior) {
    __shared__ float red[8];
    int t = threadIdx.x;
    float s = 0.f;
    for (int i = t; i < S_; i += 256) s += prior[i];
    for (int o = 16; o; o >>= 1) s += __shfl_down_sync(0xffffffffu, s, o);
    if ((t & 31) == 0) red[t >> 5] = s;
    __syncthreads();
    float tot = 0.f;
    #pragma unroll
    for (int i = 0; i < 8; i++) tot += red[i];
    float inv = 1.f / tot;
    for (int i = t; i < S_; i += 256) {
        float p = prior[i] * inv;
        float c = p * (float)S_ - 1.f;
        float g = 1.f + 0.5f * c;
        g_gamma[i] = fminf(fmaxf(g, 0.8f), 1.25f);
        g_eta[i]   = fminf(fmaxf(g, 0.9f), 1.1f);
        g_delta[i] = fminf(fmaxf(logf(p + 1e-8f), -2.f), 2.f);
        g_post[i]  = 0.5f * logf(p * (float)S_);
    }
}

// ---------------- fp32 -> (hi, lo) bf16 split ----------------
__global__ __launch_bounds__(256) void split_kernel(const float* __restrict__ x,
                                                    __nv_bfloat16* __restrict__ hi,
                                                    __nv_bfloat16* __restrict__ lo) {
    int i = (blockIdx.x * 256 + threadIdx.x) * 4;
    float4 v = *(const float4*)(x + i);
    float a0 = v.x, a1 = v.y, a2 = v.z, a3 = v.w;
    __nv_bfloat16 h0 = __float2bfloat16(a0), h1 = __float2bfloat16(a1);
    __nv_bfloat16 h2 = __float2bfloat16(a2), h3 = __float2bfloat16(a3);
    __nv_bfloat16 l0 = __float2bfloat16(a0 - __bfloat162float(h0));
    __nv_bfloat16 l1 = __float2bfloat16(a1 - __bfloat162float(h1));
    __nv_bfloat16 l2 = __float2bfloat16(a2 - __bfloat162float(h2));
    __nv_bfloat16 l3 = __float2bfloat16(a3 - __bfloat162float(h3));
    *(__nv_bfloat162*)(hi + i)     = __nv_bfloat162(h0, h1);
    *(__nv_bfloat162*)(hi + i + 2) = __nv_bfloat162(h2, h3);
    *(__nv_bfloat162*)(lo + i)     = __nv_bfloat162(l0, l1);
    *(__nv_bfloat162*)(lo + i + 2) = __nv_bfloat162(l2, l3);
}

// ---------------- transpose + split (weights) ----------------
__global__ __launch_bounds__(256) void tsplit_kernel(const float* __restrict__ W,
                                                     __nv_bfloat16* __restrict__ Th,
                                                     __nv_bfloat16* __restrict__ Tl,
                                                     int K, int N) {
    __shared__ float ts[32][33];
    int tx = threadIdx.x & 31, ty = threadIdx.x >> 5;
    int k0 = blockIdx.y << 5, n0 = blockIdx.x << 5;
    #pragma unroll
    for (int i = 0; i < 4; i++)
        ts[ty + 8 * i][tx] = W[(size_t)(k0 + ty + 8 * i) * N + n0 + tx];
    __syncthreads();
    #pragma unroll
    for (int i = 0; i < 4; i++) {
        int nl = ty + 8 * i;
        float x = ts[tx][nl];
        __nv_bfloat16 h = __float2bfloat16(x);
        __nv_bfloat16 l = __float2bfloat16(x - __bfloat162float(h));
        size_t o = (size_t)(n0 + nl) * K + k0 + tx;
        Th[o] = h;
        Tl[o] = l;
    }
}

// ---------------- V: eta-scale + transpose + split ----------------
// grid (S/32, HD/32, B*NKV), block 256. g_vraw[b*S+s][kv*HD+d] -> g_vth/l[(b*NKV+kv)*HD+d][s]
__global__ __launch_bounds__(256) void vtsplit_kernel() {
    __shared__ float ts[32][33];
    int bk = blockIdx.z;
    int b = bk >> 3, kv = bk & 7;
    int s0 = blockIdx.x << 5, d0 = blockIdx.y << 5;
    int tx = threadIdx.x & 31, ty = threadIdx.x >> 5;
    #pragma unroll
    for (int i = 0; i < 4; i++) {
        int s = s0 + ty + 8 * i;
        ts[ty + 8 * i][tx] = g_vraw[(size_t)(b * S_ + s) * (NKV * HD) + kv * HD + d0 + tx]
                             * g_eta[s];
    }
    __syncthreads();
    #pragma unroll
    for (int i = 0; i < 4; i++) {
        int d = d0 + ty + 8 * i;
        float x = ts[tx][ty + 8 * i];
        __nv_bfloat16 h = __float2bfloat16(x);
        size_t o = ((size_t)(b * NKV + kv) * HD + d) * S_ + s0 + tx;
        g_vth[o] = h;
        g_vtl[o] = __float2bfloat16(x - __bfloat162float(h));
    }
}

// ---------------- bf16 split GEMM via mma.sync (proven R7/R8) ----------------
#define GEMM_SMEM 81920
__global__ __launch_bounds__(256) void gemm_mma_kernel(
    const __nv_bfloat16* __restrict__ Ah, const __nv_bfloat16* __restrict__ Al,
    const __nv_bfloat16* __restrict__ Bh, const __nv_bfloat16* __restrict__ Bl,
    float* __restrict__ C, int N, int K)
{
    extern __shared__ char gsm[];
    uint32_t sb = smem_u32(gsm);
    int tid = threadIdx.x, w = tid >> 5, lane = tid & 31;
    int wm = (w >> 2) * 64, wn = (w & 3) * 32;
    int row0 = blockIdx.y << 7, col0 = blockIdx.x << 7;

    const __nv_bfloat16* gp[4] = {Ah, Al, Bh, Bl};

    auto stage_load = [&](int kc, int s) {
        uint32_t base = sb + (uint32_t)s * 40960u;
        #pragma unroll
        for (int i = 0; i < 8; i++) {
            int it = i * 256 + tid;
            int t  = it >> 9;
            int r  = (it >> 2) & 127;
            int j  = it & 3;
            const __nv_bfloat16* g = gp[t] + (size_t)((t < 2 ? row0 : col0) + r) * K + kc + j * 8;
            uint32_t dst = base + (uint32_t)t * 10240u + (uint32_t)r * 80u + (uint32_t)j * 16u;
            CP16(dst, g);
        }
        asm volatile("cp.async.commit_group;");
    };

    float acc[4][4][4];
    #pragma unroll
    for (int a = 0; a < 4; a++)
        #pragma unroll
        for (int b = 0; b < 4; b++)
            #pragma unroll
            for (int c = 0; c < 4; c++) acc[a][b][c] = 0.f;

    stage_load(0, 0);

    for (int kc = 0; kc < K; kc += 32) {
        int s = (kc >> 5) & 1;
        if (kc + 32 < K) {
            stage_load(kc + 32, s ^ 1);
            asm volatile("cp.async.wait_group 1;");
        } else {
            asm volatile("cp.async.wait_group 0;");
        }
        __syncthreads();

        uint32_t base = sb + (uint32_t)s * 40960u;
        uint32_t ahB = base, alB = base + 10240u, bhB = base + 20480u, blB = base + 30720u;

        #pragma unroll
        for (int ks = 0; ks < 32; ks += 16) {
            uint32_t aoff = (uint32_t)((lane & 15)) * 80u + (uint32_t)(ks + ((lane >> 4) << 3)) * 2u;
            uint32_t boff = (uint32_t)((lane & 7)) * 80u + (uint32_t)(ks + ((lane >> 3) & 1) * 8) * 2u;

            uint32_t ah[4][4], al[4][4], bh[4][2], bl[4][2];
            #pragma unroll
            for (int mt = 0; mt < 4; mt++) {
                uint32_t ra = (uint32_t)(wm + mt * 16) * 80u + aoff;
                LDSM_X4(ah[mt], ahB + ra);
                LDSM_X4(al[mt], alB + ra);
            }
            #pragma unroll
            for (int nt = 0; nt < 4; nt++) {
                uint32_t rb = (uint32_t)(wn + nt * 8) * 80u + boff;
                LDSM_X2(bh[nt], bhB + rb);
                LDSM_X2(bl[nt], blB + rb);
            }
            #pragma unroll
            for (int mt = 0; mt < 4; mt++) {
                #pragma unroll
                for (int nt = 0; nt < 4; nt++) {
                    MMA_BF16(acc[mt][nt], ah[mt], bh[nt]);
                    MMA_BF16(acc[mt][nt], ah[mt], bl[nt]);
                    MMA_BF16(acc[mt][nt], al[mt], bh[nt]);
                }
            }
        }
        __syncthreads();
    }

    int er = lane >> 2, ec = (lane & 3) << 1;
    #pragma unroll
    for (int mt = 0; mt < 4; mt++) {
        #pragma unroll
        for (int nt = 0; nt < 4; nt++) {
            float* Cp = C + (size_t)(row0 + wm + mt * 16 + er) * N + col0 + wn + nt * 8 + ec;
            *(float2*)Cp           = make_float2(acc[mt][nt][0], acc[mt][nt][1]);
            *(float2*)(Cp + 8 * N) = make_float2(acc[mt][nt][2], acc[mt][nt][3]);
        }
    }
}

// ---------------- RMSnorm + RoPE + scale + split (Q, K only) ----------------
// grid (MTOK, NH + NKV), block 128.
__global__ __launch_bounds__(128) void transform_kernel(const float* __restrict__ cosb,
                                                        const float* __restrict__ sinb,
                                                        const float* __restrict__ qw,
                                                        const float* __restrict__ kw) {
    int m = blockIdx.x;
    int z = blockIdx.y;
    int d = threadIdx.x;
    int b = m >> 11, s = m & 2047;

    __shared__ float sh[HD];
    __shared__ float red[4];

    int mode_q = (z < NH);
    int h = mode_q ? z : (z - NH);
    const float* src = mode_q ? (g_qraw + (size_t)m * (NH * HD) + h * HD)
                              : (g_kraw + (size_t)m * (NKV * HD) + h * HD);
    float x = src[d];
    sh[d] = x;
    float v2 = x * x;
    for (int o = 16; o; o >>= 1) v2 += __shfl_down_sync(0xffffffffu, v2, o);
    if ((d & 31) == 0) red[d >> 5] = v2;
    __syncthreads();
    float sum = red[0] + red[1] + red[2] + red[3];
    float rsq = rsqrtf(sum * (1.f / 128.f) + 1e-6f);
    const float* wn = mode_q ? qw : kw;
    float val = x * rsq * wn[d];
    float pv  = sh[d ^ 64] * rsq * wn[d ^ 64];
    float rot = (d < 64) ? -pv : pv;
    size_t ci = (size_t)m * HD + d;
    float o = val * cosb[ci] + rot * sinb[ci];
    if (mode_q) {
        o *= SCALING;
        size_t idx = ((size_t)(b * NH + h) * S_ + s) * HD + d;
        __nv_bfloat16 hx = __float2bfloat16(o);
        g_qh[idx] = hx;
        g_ql[idx] = __float2bfloat16(o - __bfloat162float(hx));
    } else {
        o *= g_gamma[s];
        size_t idx = ((size_t)(b * NKV + h) * S_ + s) * HD + d;
        __nv_bfloat16 hx = __float2bfloat16(o);
        g_kh[idx] = hx;
        g_kl[idx] = __float2bfloat16(o - __bfloat162float(hx));
    }
}

// ---------------- tensor-core flash attention (cp.async staging) ----------------
#define AQ_STRIDE 272
#define AV_STRIDE 80
#define A_QH 0
#define A_QL 17408
#define A_KH 34816
#define A_KL 43520
#define A_VH 52224
#define A_VL 62464
#define A_BS 72704
#define ATTN_SMEM 72832
__global__ __launch_bounds__(128) void attn_mma_kernel(const float* __restrict__ m1,
                                                       const float* __restrict__ m2) {
    extern __shared__ char asmem[];
    uint32_t sb = smem_u32(asmem);
    float* biasS = (float*)(asmem + A_BS);

    int bh = blockIdx.y;
    int b = bh >> 4, h = bh & 15, hk = h >> 1;
    int q0 = blockIdx.x << 6;
    int tid = threadIdx.x, w = tid >> 5, lane = tid & 31;
    int r = lane >> 2;
    int rowA = q0 + w * 16 + r;
    int rowB = rowA + 8;

    size_t qbase = (size_t)(b * NH + h) * S_ + q0;
    size_t kbase = (size_t)(b * NKV + hk) * S_;
    size_t vbase = (size_t)(b * NKV + hk) * HD;
    float m1h = m1[h], m2h = m2[h];

    // ---- stage Q once via cp.async (64 rows x 256B, hi+lo) ----
    for (int it = tid; it < 2048; it += 128) {
        int half = it >> 10;
        int rr = (it >> 4) & 63;
        int c  = it & 15;
        const __nv_bfloat16* src = (half ? g_ql : g_qh) + (qbase + rr) * HD + c * 8;
        uint32_t dst = sb + (half ? A_QL : A_QH) + rr * AQ_STRIDE + c * 16;
        CP16(dst, src);
    }
    asm volatile("cp.async.commit_group;");

    float O[16][4];
    #pragma unroll
    for (int nt = 0; nt < 16; nt++)
        #pragma unroll
        for (int j = 0; j < 4; j++) O[nt][j] = 0.f;
    float mA = -3e38f, mB = -3e38f, lA = 0.f, lB = 0.f;

    int nkt = (q0 >> 5) + 2;
    for (int kt = 0; kt < nkt; kt++) {
        int k0 = kt << 5;
        __syncthreads();   // previous tile's reads done
        // ---- stage K tile (32 rows x 256B, hi+lo) ----
        for (int it = tid; it < 1024; it += 128) {
            int half = it >> 9;
            int rr = (it >> 4) & 31;
            int c  = it & 15;
            const __nv_bfloat16* src = (half ? g_kl : g_kh) + (kbase + k0 + rr) * HD + c * 8;
            uint32_t dst = sb + (half ? A_KL : A_KH) + rr * AQ_STRIDE + c * 16;
            CP16(dst, src);
        }
        // ---- stage Vt tile (128 d-rows x 64B, hi+lo) ----
        for (int it = tid; it < 1024; it += 128) {
            int half = it >> 9;
            int d = (it >> 2) & 127;
            int c = it & 3;
            const __nv_bfloat16* src = (half ? g_vtl : g_vth) + (vbase + d) * S_ + k0 + c * 8;
            uint32_t dst = sb + (half ? A_VL : A_VH) + d * AV_STRIDE + c * 16;
            CP16(dst, src);
        }
        if (tid < 32) biasS[tid] = m1h * g_delta[k0 + tid] + m2h * g_post[k0 + tid];
        asm volatile("cp.async.commit_group;");
        asm volatile("cp.async.wait_group 0;");
        __syncthreads();

        // ---- S = Q*K^T ----
        float S[4][4];
        #pragma unroll
        for (int nt = 0; nt < 4; nt++)
            #pragma unroll
            for (int j = 0; j < 4; j++) S[nt][j] = 0.f;

        uint32_t aoff = (uint32_t)(w * 16 + (lane & 15)) * AQ_STRIDE +
                        (uint32_t)(((lane >> 4) << 3)) * 2u;
        uint32_t boff = (uint32_t)((lane & 7)) * AQ_STRIDE +
                        (uint32_t)(((lane >> 3) & 1) * 8) * 2u;
        #pragma unroll
        for (int ks = 0; ks < 8; ks++) {
            uint32_t ka = aoff + ks * 32u;
            uint32_t qh[4], ql[4];
            LDSM_X4(qh, sb + A_QH + ka);
            LDSM_X4(ql, sb + A_QL + ka);
            #pragma unroll
            for (int nt = 0; nt < 4; nt++) {
                uint32_t kb = boff + (uint32_t)(nt * 8) * AQ_STRIDE + ks * 32u;
                uint32_t bh2[2], bl2[2];
                LDSM_X2(bh2, sb + A_KH + kb);
                LDSM_X2(bl2, sb + A_KL + kb);
                MMA_BF16(S[nt], qh, bh2);
                MMA_BF16(S[nt], qh, bl2);
                MMA_BF16(S[nt], ql, bh2);
            }
        }

        // ---- bias + causal mask ----
        int cbase = 2 * (lane & 3);
        bool need_mask = (k0 + 31 > q0);
        #pragma unroll
        for (int nt = 0; nt < 4; nt++) {
            int c0l = nt * 8 + cbase;
            float b0 = biasS[c0l], b1 = biasS[c0l + 1];
            S[nt][0] += b0; S[nt][1] += b1;
            S[nt][2] += b0; S[nt][3] += b1;
            if (need_mask) {
                int c0g = k0 + c0l;
                if (c0g > rowA)     S[nt][0] = -3e38f;
                if (c0g + 1 > rowA) S[nt][1] = -3e38f;
                if (c0g > rowB)     S[nt][2] = -3e38f;
                if (c0g + 1 > rowB) S[nt][3] = -3e38f;
            }
        }

        // ---- online softmax ----
        float cmA = -3e38f, cmB = -3e38f;
        #pragma unroll
        for (int nt = 0; nt < 4; nt++) {
            cmA = fmaxf(cmA, fmaxf(S[nt][0], S[nt][1]));
            cmB = fmaxf(cmB, fmaxf(S[nt][2], S[nt][3]));
        }
        cmA = fmaxf(cmA, __shfl_xor_sync(0xffffffffu, cmA, 1));
        cmA = fmaxf(cmA, __shfl_xor_sync(0xffffffffu, cmA, 2));
        cmB = fmaxf(cmB, __shfl_xor_sync(0xffffffffu, cmB, 1));
        cmB = fmaxf(cmB, __shfl_xor_sync(0xffffffffu, cmB, 2));
        float mnA = fmaxf(mA, cmA), mnB = fmaxf(mB, cmB);
        float sumA = 0.f, sumB = 0.f;
        #pragma unroll
        for (int nt = 0; nt < 4; nt++) {
            S[nt][0] = __expf(S[nt][0] - mnA);
            S[nt][1] = __expf(S[nt][1] - mnA);
            S[nt][2] = __expf(S[nt][2] - mnB);
            S[nt][3] = __expf(S[nt][3] - mnB);
            sumA += S[nt][0] + S[nt][1];
            sumB += S[nt][2] + S[nt][3];
        }
        sumA += __shfl_xor_sync(0xffffffffu, sumA, 1);
        sumA += __shfl_xor_sync(0xffffffffu, sumA, 2);
        sumB += __shfl_xor_sync(0xffffffffu, sumB, 1);
        sumB += __shfl_xor_sync(0xffffffffu, sumB, 2);
        float scA = __expf(mA - mnA), scB = __expf(mB - mnB);
        lA = lA * scA + sumA; lB = lB * scB + sumB;
        mA = mnA; mB = mnB;
        #pragma unroll
        for (int nt = 0; nt < 16; nt++) {
            O[nt][0] *= scA; O[nt][1] *= scA;
            O[nt][2] *= scB; O[nt][3] *= scB;
        }

        // ---- P fragments; PV over d ----
        uint32_t vboff = (uint32_t)((lane & 7)) * AV_STRIDE +
                         (uint32_t)(((lane >> 3) & 1) * 8) * 2u;
        #pragma unroll
        for (int sk = 0; sk < 2; sk++) {
            float* t0 = S[2 * sk];
            float* t1 = S[2 * sk + 1];
            uint32_t ph[4], pl[4];
            ph[0] = pack_bf2(t0[0], t0[1]);
            ph[1] = pack_bf2(t0[2], t0[3]);
            ph[2] = pack_bf2(t1[0], t1[1]);
            ph[3] = pack_bf2(t1[2], t1[3]);
            pl[0] = pack_bf2(t0[0] - bf_hi_f(t0[0]), t0[1] - bf_hi_f(t0[1]));
            pl[1] = pack_bf2(t0[2] - bf_hi_f(t0[2]), t0[3] - bf_hi_f(t0[3]));
            pl[2] = pack_bf2(t1[0] - bf_hi_f(t1[0]), t1[1] - bf_hi_f(t1[1]));
            pl[3] = pack_bf2(t1[2] - bf_hi_f(t1[2]), t1[3] - bf_hi_f(t1[3]));
            #pragma unroll
            for (int nt = 0; nt < 16; nt++) {
                uint32_t vb = vboff + (uint32_t)(nt * 8) * AV_STRIDE + (uint32_t)(sk * 16) * 2u;
                uint32_t vh2[2], vl2[2];
                LDSM_X2(vh2, sb + A_VH + vb);
                LDSM_X2(vl2, sb + A_VL + vb);
                MMA_BF16(O[nt], ph, vh2);
                MMA_BF16(O[nt], ph, vl2);
                MMA_BF16(O[nt], pl, vh2);
            }
        }
    }

    float invA = 1.f / lA, invB = 1.f / lB;
    float* oA = g_ao + (size_t)(b * S_ + rowA) * (NH * HD) + h * HD;
    float* oB = g_ao + (size_t)(b * S_ + rowB) * (NH * HD) + h * HD;
    int ec = 2 * (lane & 3);
    #pragma unroll
    for (int nt = 0; nt < 16; nt++) {
        int c = nt * 8 + ec;
        *(float2*)(oA + c) = make_float2(O[nt][0] * invA, O[nt][1] * invA);
        *(float2*)(oB + c) = make_float2(O[nt][2] * invB, O[nt][3] * invB);
    }
}

// ---------------- launch ----------------
extern "C" void kernel_launch(void* const* d_in, const int* in_sizes, int n_in,
                              void* d_out, int out_size) {
    const float* hidden = (const float*)d_in[0];
    const float* cosb   = (const float*)d_in[1];
    const float* sinb   = (const float*)d_in[2];
    const float* prior  = (const float*)d_in[4];
    const float* m1     = (const float*)d_in[5];
    const float* m2     = (const float*)d_in[6];
    const float* Wq     = (const float*)d_in[7];
    const float* Wk     = (const float*)d_in[8];
    const float* Wv     = (const float*)d_in[9];
    const float* Wo     = (const float*)d_in[10];
    const float* qw     = (const float*)d_in[11];
    const float* kw     = (const float*)d_in[12];
    float* out = (float*)d_out;

    float *qraw, *kraw, *vraw, *ao;
    __nv_bfloat16 *ahi, *alo, *aoh, *aol;
    __nv_bfloat16 *wqh, *wql, *wkh, *wkl, *wvh, *wvl, *woh, *wol;
    cudaGetSymbolAddress((void**)&qraw, g_qraw);
    cudaGetSymbolAddress((void**)&kraw, g_kraw);
    cudaGetSymbolAddress((void**)&vraw, g_vraw);
    cudaGetSymbolAddress((void**)&ao,   g_ao);
    cudaGetSymbolAddress((void**)&ahi,  g_ahi);
    cudaGetSymbolAddress((void**)&alo,  g_alo);
    cudaGetSymbolAddress((void**)&aoh,  g_aoh);
    cudaGetSymbolAddress((void**)&aol,  g_aol);
    cudaGetSymbolAddress((void**)&wqh,  g_wqt_h);
    cudaGetSymbolAddress((void**)&wql,  g_wqt_l);
    cudaGetSymbolAddress((void**)&wkh,  g_wkt_h);
    cudaGetSymbolAddress((void**)&wkl,  g_wkt_l);
    cudaGetSymbolAddress((void**)&wvh,  g_wvt_h);
    cudaGetSymbolAddress((void**)&wvl,  g_wvt_l);
    cudaGetSymbolAddress((void**)&woh,  g_wot_h);
    cudaGetSymbolAddress((void**)&wol,  g_wot_l);

    cudaFuncSetAttribute(attn_mma_kernel, cudaFuncAttributeMaxDynamicSharedMemorySize, ATTN_SMEM);
    cudaFuncSetAttribute(gemm_mma_kernel, cudaFuncAttributeMaxDynamicSharedMemorySize, GEMM_SMEM);

    prep_kernel<<<1, 256>>>(prior);

    split_kernel<<<(MTOK * HID) / 1024, 256>>>(hidden, ahi, alo);
    tsplit_kernel<<<dim3(64, 64), 256>>>(Wq, wqh, wql, 2048, 2048);
    tsplit_kernel<<<dim3(32, 64), 256>>>(Wk, wkh, wkl, 2048, 1024);
    tsplit_kernel<<<dim3(32, 64), 256>>>(Wv, wvh, wvl, 2048, 1024);
    tsplit_kernel<<<dim3(64, 64), 256>>>(Wo, woh, wol, 2048, 2048);

    gemm_mma_kernel<<<dim3(16, 32), 256, GEMM_SMEM>>>(ahi, alo, wqh, wql, qraw, 2048, 2048);
    gemm_mma_kernel<<<dim3(8, 32),  256, GEMM_SMEM>>>(ahi, alo, wkh, wkl, kraw, 1024, 2048);
    gemm_mma_kernel<<<dim3(8, 32),  256, GEMM_SMEM>>>(ahi, alo, wvh, wvl, vraw, 1024, 2048);

    transform_kernel<<<dim3(MTOK, NH + NKV), 128>>>(cosb, sinb, qw, kw);
    vtsplit_kernel<<<dim3(S_ / 32, HD / 32, B_ * NKV), 256>>>();

    attn_mma_kernel<<<dim3(S_ / 64, B_ * NH), 128, ATTN_SMEM>>>(m1, m2);

    split_kernel<<<(MTOK * HID) / 1024, 256>>>(ao, aoh, aol);
    gemm_mma_kernel<<<dim3(16, 32), 256, GEMM_SMEM>>>(aoh, aol, woh, wol, out, 2048, 2048);
}